// round 14
// baseline (speedup 1.0000x reference)
#include <cuda_runtime.h>
#include <cuda_bf16.h>
#include <cstdint>

#define D 128
#define D4 32
#define MAXN 50176
#define MAXE 800000

typedef unsigned long long ull;

// ---- scratch (module-static device memory, zero-initialized at load) ----
__device__ __align__(16) float g_h[MAXN * D];           // fp32 h (agg + fallback)
__device__ __align__(16) float g_par[MAXN * D];         // partial = h @ Wl
__device__ __align__(16) unsigned short g_ha[MAXN * D]; // h hi bf16, pre-swizzled
__device__ __align__(16) unsigned short g_la[MAXN * D]; // h lo bf16
__device__ __align__(16) unsigned short g_za[MAXN * D]; // z hi bf16
__device__ __align__(16) unsigned short g_zl[MAXN * D]; // z lo bf16
__device__ int   g_cnt[MAXN];
__device__ int   g_off[MAXN];                           // chunk-local CSR offsets
__device__ int   g_bsum[128];
__device__ __align__(8) int2 g_edge[MAXE];

// ---- side stream + events, created at static-init (no device allocation) ----
static cudaStream_t g_s2 = nullptr;
static cudaEvent_t  g_ev1 = nullptr, g_ev2 = nullptr;
namespace {
struct StreamInit {
    StreamInit() {
        if (cudaStreamCreateWithFlags(&g_s2, cudaStreamNonBlocking) != cudaSuccess)
            g_s2 = nullptr;
        if (cudaEventCreateWithFlags(&g_ev1, cudaEventDisableTiming) != cudaSuccess)
            g_ev1 = nullptr;
        if (cudaEventCreateWithFlags(&g_ev2, cudaEventDisableTiming) != cudaSuccess)
            g_ev2 = nullptr;
    }
} g_si;
}

__device__ __forceinline__ void split2(float x0, float x1,
                                       uint32_t& hi, uint32_t& lo) {
    __nv_bfloat16 h0 = __float2bfloat16(x0);
    __nv_bfloat16 h1 = __float2bfloat16(x1);
    __nv_bfloat16 l0 = __float2bfloat16(x0 - __bfloat162float(h0));
    __nv_bfloat16 l1 = __float2bfloat16(x1 - __bfloat162float(h1));
    hi = (uint32_t)__bfloat16_as_ushort(h0) |
         ((uint32_t)__bfloat16_as_ushort(h1) << 16);
    lo = (uint32_t)__bfloat16_as_ushort(l0) |
         ((uint32_t)__bfloat16_as_ushort(l1) << 16);
}

// ---------------------------------------------------------------------------
// K1: grid-split: gather h (fp32 + pre-swizzled bf16 hi/lo)  |  histogram dst
// ---------------------------------------------------------------------------
__global__ void k_prep(const float* __restrict__ prev,
                       const int* __restrict__ node_id,
                       const int* __restrict__ dst,
                       int n, int ne, int gb)
{
    if (blockIdx.x < gb) {
        int i = blockIdx.x * 256 + threadIdx.x;
        if (i >= n * D4) return;
        int row = i >> 5, col = i & 31;
        int ent = __ldg(node_id + row);
        float4 v = __ldg(reinterpret_cast<const float4*>(prev) + (size_t)ent * D4 + col);
        reinterpret_cast<float4*>(g_h)[i] = v;
        uint32_t h01, l01, h23, l23;
        split2(v.x, v.y, h01, l01);
        split2(v.z, v.w, h23, l23);
        int off = ((col >> 1) ^ (row & 7)) * 16 + (col & 1) * 8;
        *reinterpret_cast<uint2*>((char*)g_ha + (size_t)row * 256 + off) = make_uint2(h01, h23);
        *reinterpret_cast<uint2*>((char*)g_la + (size_t)row * 256 + off) = make_uint2(l01, l23);
    } else {
        int e = (blockIdx.x - gb) * 256 + threadIdx.x;
        if (e >= ne) return;
        atomicAdd(&g_cnt[__ldg(dst + e)], 1);
    }
}

// ---------------------------------------------------------------------------
// K2: per-chunk exclusive scan of g_cnt -> g_off (chunk-local); totals->g_bsum
// ---------------------------------------------------------------------------
__global__ void k_scan1(int n)
{
    __shared__ int sm[1024];
    int t = threadIdx.x;
    int i = blockIdx.x * 1024 + t;
    int v = (i < n) ? g_cnt[i] : 0;
    sm[t] = v;
    __syncthreads();
    #pragma unroll
    for (int off = 1; off < 1024; off <<= 1) {
        int x = (t >= off) ? sm[t - off] : 0;
        __syncthreads();
        sm[t] += x;
        __syncthreads();
    }
    if (i < n) g_off[i] = sm[t] - v;
    if (t == 1023) g_bsum[blockIdx.x] = sm[t];
}

// ---------------------------------------------------------------------------
// K3: counting-sort edges by dst (R11-proven)
// ---------------------------------------------------------------------------
__global__ void k_perm(const int* __restrict__ src, const int* __restrict__ dst,
                       const int* __restrict__ ety, int ne, int nchunks)
{
    __shared__ int pre[128];
    int t = threadIdx.x;
    if (t == 0) {
        int run = 0;
        for (int j = 0; j < nchunks; j++) { pre[j] = run; run += g_bsum[j]; }
    }
    __syncthreads();
    int e = blockIdx.x * 256 + t;
    if (e >= ne) return;
    int d = __ldg(dst + e);
    int pos = pre[d >> 10] + atomicAdd(&g_off[d], 1);
    g_edge[pos] = make_int2(__ldg(src + e), __ldg(ety + e));
}

// ---------------------------------------------------------------------------
// K4: one warp per node: z = (1/cnt) * sum_e (h[src_e] + rel[etype_e]);
// (R11-proven); writes z as bf16 hi/lo.
// ---------------------------------------------------------------------------
__global__ void k_agg(const float* __restrict__ rel, int n, int nchunks)
{
    __shared__ int pre[128];
    if (threadIdx.x == 0) {
        int run = 0;
        for (int j = 0; j < nchunks; j++) { pre[j] = run; run += g_bsum[j]; }
    }
    __syncthreads();

    int lane = threadIdx.x & 31;
    int node = (blockIdx.x * blockDim.x + threadIdx.x) >> 5;
    if (node >= n) return;
    int cnt = __ldg(&g_cnt[node]);
    int beg = pre[node >> 10] + __ldg(&g_off[node]) - cnt;

    const float4* h4 = reinterpret_cast<const float4*>(g_h);
    const float4* r4 = reinterpret_cast<const float4*>(rel);

    float4 acc = make_float4(0.f, 0.f, 0.f, 0.f);
    int j = 0;
    for (; j + 3 < cnt; j += 4) {
        int2 e0 = __ldg(&g_edge[beg + j]);
        int2 e1 = __ldg(&g_edge[beg + j + 1]);
        int2 e2 = __ldg(&g_edge[beg + j + 2]);
        int2 e3 = __ldg(&g_edge[beg + j + 3]);
        float4 a0 = __ldcg(h4 + e0.x * D4 + lane);
        float4 a1 = __ldcg(h4 + e1.x * D4 + lane);
        float4 a2 = __ldcg(h4 + e2.x * D4 + lane);
        float4 a3 = __ldcg(h4 + e3.x * D4 + lane);
        float4 b0 = __ldg(r4 + e0.y * D4 + lane);
        float4 b1 = __ldg(r4 + e1.y * D4 + lane);
        float4 b2 = __ldg(r4 + e2.y * D4 + lane);
        float4 b3 = __ldg(r4 + e3.y * D4 + lane);
        acc.x += ((a0.x + b0.x) + (a1.x + b1.x)) + ((a2.x + b2.x) + (a3.x + b3.x));
        acc.y += ((a0.y + b0.y) + (a1.y + b1.y)) + ((a2.y + b2.y) + (a3.y + b3.y));
        acc.z += ((a0.z + b0.z) + (a1.z + b1.z)) + ((a2.z + b2.z) + (a3.z + b3.z));
        acc.w += ((a0.w + b0.w) + (a1.w + b1.w)) + ((a2.w + b2.w) + (a3.w + b3.w));
    }
    for (; j < cnt; j++) {
        int2 e0 = __ldg(&g_edge[beg + j]);
        float4 a0 = __ldcg(h4 + e0.x * D4 + lane);
        float4 b0 = __ldg(r4 + e0.y * D4 + lane);
        acc.x += a0.x + b0.x;
        acc.y += a0.y + b0.y;
        acc.z += a0.z + b0.z;
        acc.w += a0.w + b0.w;
    }
    float inv = (cnt > 0) ? 1.0f / (float)cnt : 0.f;
    acc.x *= inv; acc.y *= inv; acc.z *= inv; acc.w *= inv;

    uint32_t h01, l01, h23, l23;
    split2(acc.x, acc.y, h01, l01);
    split2(acc.z, acc.w, h23, l23);
    int off = ((lane >> 1) ^ (node & 7)) * 16 + (lane & 1) * 8;
    *reinterpret_cast<uint2*>((char*)g_za + (size_t)node * 256 + off) = make_uint2(h01, h23);
    *reinterpret_cast<uint2*>((char*)g_zl + (size_t)node * 256 + off) = make_uint2(l01, l23);
}

// ===========================================================================
// GEMM halves (mma.sync bf16-split, pipelined 2-stage: X-hi, X-lo).
// k_outH: par = h @ Wl (overlaps agg on side stream)
// k_outZ: out = relu(z @ Wn + par); deg==0 -> relu(h @ We); resets g_cnt.
// ===========================================================================

#define OFF_BHI 0
#define OFF_BLO 32768
#define OFF_S0  65536
#define OFF_S1  98304
#define OFF_DEG 131072
#define SMEM_G  (131072 + 512)

__device__ __forceinline__ uint32_t smem_u32(const void* p) {
    uint32_t a;
    asm("{ .reg .u64 t; cvta.to.shared.u64 t, %1; cvt.u32.u64 %0, t; }"
        : "=r"(a) : "l"(p));
    return a;
}
__device__ __forceinline__ void cpa16(uint32_t dst, const void* src) {
    asm volatile("cp.async.cg.shared.global [%0], [%1], 16;"
                 :: "r"(dst), "l"(src) : "memory");
}
__device__ __forceinline__ void ldsm4(uint32_t* r, uint32_t addr) {
    asm volatile("ldmatrix.sync.aligned.m8n8.x4.shared.b16 {%0,%1,%2,%3}, [%4];"
                 : "=r"(r[0]), "=r"(r[1]), "=r"(r[2]), "=r"(r[3]) : "r"(addr));
}
__device__ __forceinline__ void mma16816(float* c, const uint32_t* a,
                                         const uint32_t* b) {
    asm volatile("mma.sync.aligned.m16n8k16.row.col.f32.bf16.bf16.f32 "
                 "{%0,%1,%2,%3}, {%4,%5,%6,%7}, {%8,%9}, {%0,%1,%2,%3};"
                 : "+f"(c[0]), "+f"(c[1]), "+f"(c[2]), "+f"(c[3])
                 : "r"(a[0]), "r"(a[1]), "r"(a[2]), "r"(a[3]),
                   "r"(b[0]), "r"(b[1]));
}

// Shared device body: one GEMM half with pipelined A stages.
// isZ = false: A = (g_ha, g_la), W staged, epilogue stores acc to g_par.
// isZ = true:  A = (g_za, g_zl), W staged, epilogue adds g_par, relu, deg.
template <bool isZ>
__device__ __forceinline__ void gemm_half(
    const float* __restrict__ W,        // 128x128 fp32, row = k
    const float* __restrict__ We,       // only for isZ fallback
    float* __restrict__ out,            // only for isZ
    int n)
{
    extern __shared__ __align__(16) char smem[];
    int* degs = reinterpret_cast<int*>(smem + OFF_DEG);
    uint32_t sBhi = smem_u32(smem + OFF_BHI);
    uint32_t sBlo = smem_u32(smem + OFF_BLO);
    uint32_t slot[2] = { smem_u32(smem + OFF_S0), smem_u32(smem + OFF_S1) };

    int tid = threadIdx.x, lane = tid & 31, wid = tid >> 5;
    int wm = wid & 3, wn = wid >> 2;      // 4x4 warp grid
    int rr = lane & 7, q = lane >> 3;
    int ca_q = (q >> 1);
    int m0 = wm * 32 + (q & 1) * 8 + rr;
    int m1 = m0 + 16;

    const unsigned short* Ahi = isZ ? g_za : g_ha;
    const unsigned short* Alo = isZ ? g_zl : g_la;

    // stage B = W^T [n][k], hi/lo, swizzled; rows of 128 k = 256B
    for (int i = tid; i < 128 * 16; i += 512) {
        int nn = i >> 4, c = i & 15;
        float v[8];
        #pragma unroll
        for (int j = 0; j < 8; j++)
            v[j] = __ldg(W + (c * 8 + j) * 128 + nn);
        uint32_t hi[4], lo[4];
        split2(v[0], v[1], hi[0], lo[0]);
        split2(v[2], v[3], hi[1], lo[1]);
        split2(v[4], v[5], hi[2], lo[2]);
        split2(v[6], v[7], hi[3], lo[3]);
        int cs = c ^ (nn & 7);
        *reinterpret_cast<uint4*>(smem + OFF_BHI + nn * 256 + cs * 16) =
            make_uint4(hi[0], hi[1], hi[2], hi[3]);
        *reinterpret_cast<uint4*>(smem + OFF_BLO + nn * 256 + cs * 16) =
            make_uint4(lo[0], lo[1], lo[2], lo[3]);
    }

    int ntile = (n + 127) / 128;

    // prologue: prefetch tile0's A-hi into slot0
    if ((int)blockIdx.x < ntile) {
        const char* s = (const char*)Ahi + (size_t)blockIdx.x * 128 * 256;
        #pragma unroll
        for (int j = 0; j < 4; j++) {
            int idx = tid + j * 512;
            cpa16(slot[0] + idx * 16, s + idx * 16);
        }
    }
    asm volatile("cp.async.commit_group;" ::: "memory");

    for (int tile = blockIdx.x; tile < ntile; tile += gridDim.x) {
        size_t rb = (size_t)tile * 128 * 256;
        int row0 = tile * 128;

        // issue A-lo -> slot1
        {
            const char* s = (const char*)Alo + rb;
            #pragma unroll
            for (int j = 0; j < 4; j++) {
                int idx = tid + j * 512;
                cpa16(slot[1] + idx * 16, s + idx * 16);
            }
            asm volatile("cp.async.commit_group;" ::: "memory");
        }
        asm volatile("cp.async.wait_group 1;" ::: "memory");   // A-hi ready
        __syncthreads();

        if (isZ && tid < 128) {
            int gr = row0 + tid;
            int c = 1;
            if (gr < n) { c = g_cnt[gr]; g_cnt[gr] = 0; }
            degs[tid] = c;
        }

        float acc[2][4][4];
        #pragma unroll
        for (int mt = 0; mt < 2; mt++)
            #pragma unroll
            for (int nt = 0; nt < 4; nt++)
                #pragma unroll
                for (int j2 = 0; j2 < 4; j2++) acc[mt][nt][j2] = 0.f;

        // stage0: A-hi x (B-hi + B-lo);  stage1: A-lo x B-hi
        #pragma unroll
        for (int st = 0; st < 2; st++) {
            uint32_t Ab = slot[st];
            #pragma unroll 1
            for (int kc = 0; kc < 8; kc++) {
                uint32_t a0[4], a1[4];
                int ca = kc * 2 + ca_q;
                ldsm4(a0, Ab + (uint32_t)(m0 * 256 + ((ca ^ (m0 & 7)) * 16)));
                ldsm4(a1, Ab + (uint32_t)(m1 * 256 + ((ca ^ (m1 & 7)) * 16)));
                #pragma unroll
                for (int nb = 0; nb < 2; nb++) {
                    int nn = wn * 32 + nb * 16 + (q >> 1) * 8 + rr;
                    int c = kc * 2 + (q & 1);
                    uint32_t ob = (uint32_t)(nn * 256 + ((c ^ (nn & 7)) * 16));
                    uint32_t bh[4];
                    ldsm4(bh, sBhi + ob);
                    mma16816(acc[0][2 * nb],     a0, bh);
                    mma16816(acc[0][2 * nb + 1], a0, bh + 2);
                    mma16816(acc[1][2 * nb],     a1, bh);
                    mma16816(acc[1][2 * nb + 1], a1, bh + 2);
                    if (st == 0) {
                        uint32_t bl[4];
                        ldsm4(bl, sBlo + ob);
                        mma16816(acc[0][2 * nb],     a0, bl);
                        mma16816(acc[0][2 * nb + 1], a0, bl + 2);
                        mma16816(acc[1][2 * nb],     a1, bl);
                        mma16816(acc[1][2 * nb + 1], a1, bl + 2);
                    }
                }
            }
            if (st == 0) {
                __syncthreads();           // slot0 reads done
                int nt2 = tile + gridDim.x;
                if (nt2 < ntile) {
                    const char* s = (const char*)Ahi + (size_t)nt2 * 128 * 256;
                    #pragma unroll
                    for (int j = 0; j < 4; j++) {
                        int idx = tid + j * 512;
                        cpa16(slot[0] + idx * 16, s + idx * 16);
                    }
                }
                asm volatile("cp.async.commit_group;" ::: "memory");
                asm volatile("cp.async.wait_group 1;" ::: "memory"); // A-lo ready
                __syncthreads();
            }
        }

        // epilogue
        #pragma unroll
        for (int mt = 0; mt < 2; mt++) {
            #pragma unroll
            for (int half = 0; half < 2; half++) {
                int rl = wm * 32 + mt * 16 + half * 8 + (lane >> 2);
                int gr = row0 + rl;
                if (gr >= n) continue;
                if (!isZ) {
                    #pragma unroll
                    for (int nt = 0; nt < 4; nt++) {
                        float2 o = make_float2(acc[mt][nt][2 * half],
                                               acc[mt][nt][2 * half + 1]);
                        *reinterpret_cast<float2*>(
                            g_par + (size_t)gr * 128 + wn * 32 + nt * 8 + (lane & 3) * 2) = o;
                    }
                } else if (degs[rl] != 0) {
                    #pragma unroll
                    for (int nt = 0; nt < 4; nt++) {
                        size_t oidx = (size_t)gr * 128 + wn * 32 + nt * 8 + (lane & 3) * 2;
                        float2 pv = *reinterpret_cast<const float2*>(g_par + oidx);
                        float a0 = acc[mt][nt][2 * half] + pv.x;
                        float a1 = acc[mt][nt][2 * half + 1] + pv.y;
                        float2 o = make_float2(a0 > 0.f ? a0 : 0.f,
                                               a1 > 0.f ? a1 : 0.f);
                        *reinterpret_cast<float2*>(out + oidx) = o;
                    }
                } else {
                    // rare: no in-edges -> out = relu(h @ We)
                    int cbase = (lane & 3) * 2;
                    #pragma unroll 1
                    for (int nt = 0; nt < 4; nt++) {
                        float f0 = 0.f, f1 = 0.f;
                        int col = wn * 32 + nt * 8 + cbase;
                        #pragma unroll 1
                        for (int k = 0; k < 128; k++) {
                            float hk = g_h[(size_t)gr * 128 + k];
                            f0 += hk * __ldg(We + k * 128 + col);
                            f1 += hk * __ldg(We + k * 128 + col + 1);
                        }
                        float2 o = make_float2(f0 > 0.f ? f0 : 0.f,
                                               f1 > 0.f ? f1 : 0.f);
                        *reinterpret_cast<float2*>(out + (size_t)gr * 128 + col) = o;
                    }
                }
            }
        }
        __syncthreads();   // all stage1/epilogue reads done before slot1 reuse
    }
}

__global__ void __launch_bounds__(512, 1)
k_outH(const float* __restrict__ Wl, int n)
{
    gemm_half<false>(Wl, nullptr, nullptr, n);
}

__global__ void __launch_bounds__(512, 1)
k_outZ(const float* __restrict__ Wn, const float* __restrict__ We,
       float* __restrict__ out, int n)
{
    gemm_half<true>(Wn, We, out, n);
}

// ---------------------------------------------------------------------------
extern "C" void kernel_launch(void* const* d_in, const int* in_sizes, int n_in,
                              void* d_out, int out_size)
{
    const float* prev    = (const float*)d_in[0];
    const float* rel     = (const float*)d_in[1];
    const float* Wl      = (const float*)d_in[2];
    const float* We      = (const float*)d_in[3];
    const float* Wn      = (const float*)d_in[4];
    const int*   node_id = (const int*)d_in[5];
    const int*   src     = (const int*)d_in[6];
    const int*   dst     = (const int*)d_in[7];
    const int*   ety     = (const int*)d_in[8];
    float* out = (float*)d_out;

    int n_nodes = in_sizes[5];
    int n_edges = in_sizes[6];
    int nchunks = (n_nodes + 1023) / 1024;

    static bool attrSet = false;
    if (!attrSet) {
        cudaFuncSetAttribute(k_outH, cudaFuncAttributeMaxDynamicSharedMemorySize, SMEM_G);
        cudaFuncSetAttribute(k_outZ, cudaFuncAttributeMaxDynamicSharedMemorySize, SMEM_G);
        attrSet = true;
    }

    int gb = (n_nodes * D4 + 255) / 256;
    int hb = (n_edges + 255) / 256;
    k_prep<<<gb + hb, 256>>>(prev, node_id, dst, n_nodes, n_edges, gb);

    bool forked = (g_s2 && g_ev1 && g_ev2);
    if (forked) {
        // fork: h-GEMM on side stream, overlapping scan/perm/agg
        cudaEventRecord(g_ev1, 0);
        cudaStreamWaitEvent(g_s2, g_ev1, 0);
        k_outH<<<148, 512, SMEM_G, g_s2>>>(Wl, n_nodes);
        cudaEventRecord(g_ev2, g_s2);
    } else {
        k_outH<<<148, 512, SMEM_G>>>(Wl, n_nodes);
    }

    k_scan1<<<nchunks, 1024>>>(n_nodes);
    k_perm<<<(n_edges + 255) / 256, 256>>>(src, dst, ety, n_edges, nchunks);
    k_agg<<<(n_nodes * 32 + 255) / 256, 256>>>(rel, n_nodes, nchunks);

    if (forked) cudaStreamWaitEvent(0, g_ev2, 0);   // join before combine
    k_outZ<<<148, 512, SMEM_G>>>(Wn, We, out, n_nodes);
}

// round 15
// speedup vs baseline: 1.0431x; 1.0431x over previous
#include <cuda_runtime.h>
#include <cuda_bf16.h>
#include <cstdint>

#define D 128
#define D4 32
#define MAXN 50176
#define MAXE 800000

typedef unsigned long long ull;

// ---- scratch (module-static device memory, zero-initialized at load) ----
__device__ __align__(16) float g_h[MAXN * D];           // fp32 h (agg + fallback)
__device__ __align__(16) unsigned short g_ha[MAXN * D]; // h hi bf16, pre-swizzled rows
__device__ __align__(16) unsigned short g_la[MAXN * D]; // h lo bf16
__device__ __align__(16) unsigned short g_za[MAXN * D]; // z hi bf16
__device__ __align__(16) unsigned short g_zl[MAXN * D]; // z lo bf16
__device__ int   g_cnt[MAXN];
__device__ int   g_off[MAXN];                           // chunk-local CSR offsets
__device__ int   g_bsum[128];
__device__ __align__(8) int2 g_edge[MAXE];

__device__ __forceinline__ void split2(float x0, float x1,
                                       uint32_t& hi, uint32_t& lo) {
    __nv_bfloat16 h0 = __float2bfloat16(x0);
    __nv_bfloat16 h1 = __float2bfloat16(x1);
    __nv_bfloat16 l0 = __float2bfloat16(x0 - __bfloat162float(h0));
    __nv_bfloat16 l1 = __float2bfloat16(x1 - __bfloat162float(h1));
    hi = (uint32_t)__bfloat16_as_ushort(h0) |
         ((uint32_t)__bfloat16_as_ushort(h1) << 16);
    lo = (uint32_t)__bfloat16_as_ushort(l0) |
         ((uint32_t)__bfloat16_as_ushort(l1) << 16);
}

// parallel-load + smem-serial prefix of g_bsum into pre[] (block-wide)
__device__ __forceinline__ void load_prefix(int* pre, int nchunks) {
    int t = threadIdx.x;
    if (t < nchunks) pre[t] = g_bsum[t];     // parallel coalesced loads
    __syncthreads();
    if (t == 0) {
        int run = 0;
        for (int j = 0; j < nchunks; j++) {  // smem-speed serial scan
            int x = pre[j]; pre[j] = run; run += x;
        }
    }
    __syncthreads();
}

// ---------------------------------------------------------------------------
// K1: grid-split: gather h (fp32 + pre-swizzled bf16 hi/lo)  |  histogram dst
// ---------------------------------------------------------------------------
__global__ void k_prep(const float* __restrict__ prev,
                       const int* __restrict__ node_id,
                       const int* __restrict__ dst,
                       int n, int ne, int gb)
{
    if (blockIdx.x < gb) {
        int i = blockIdx.x * 256 + threadIdx.x;
        if (i >= n * D4) return;
        int row = i >> 5, col = i & 31;
        int ent = __ldg(node_id + row);
        float4 v = __ldg(reinterpret_cast<const float4*>(prev) + (size_t)ent * D4 + col);
        reinterpret_cast<float4*>(g_h)[i] = v;
        uint32_t h01, l01, h23, l23;
        split2(v.x, v.y, h01, l01);
        split2(v.z, v.w, h23, l23);
        int off = ((col >> 1) ^ (row & 7)) * 16 + (col & 1) * 8;
        *reinterpret_cast<uint2*>((char*)g_ha + (size_t)row * 256 + off) = make_uint2(h01, h23);
        *reinterpret_cast<uint2*>((char*)g_la + (size_t)row * 256 + off) = make_uint2(l01, l23);
    } else {
        int e = (blockIdx.x - gb) * 256 + threadIdx.x;
        if (e >= ne) return;
        atomicAdd(&g_cnt[__ldg(dst + e)], 1);
    }
}

// ---------------------------------------------------------------------------
// K2: per-chunk exclusive scan of g_cnt -> g_off (chunk-local); totals->g_bsum
// ---------------------------------------------------------------------------
__global__ void k_scan1(int n)
{
    __shared__ int sm[1024];
    int t = threadIdx.x;
    int i = blockIdx.x * 1024 + t;
    int v = (i < n) ? g_cnt[i] : 0;
    sm[t] = v;
    __syncthreads();
    #pragma unroll
    for (int off = 1; off < 1024; off <<= 1) {
        int x = (t >= off) ? sm[t - off] : 0;
        __syncthreads();
        sm[t] += x;
        __syncthreads();
    }
    if (i < n) g_off[i] = sm[t] - v;
    if (t == 1023) g_bsum[blockIdx.x] = sm[t];
}

// ---------------------------------------------------------------------------
// K3: counting-sort edges by dst; fast parallel-load chunk prefix
// ---------------------------------------------------------------------------
__global__ void k_perm(const int* __restrict__ src, const int* __restrict__ dst,
                       const int* __restrict__ ety, int ne, int nchunks)
{
    __shared__ int pre[128];
    load_prefix(pre, nchunks);
    int e = blockIdx.x * 256 + threadIdx.x;
    if (e >= ne) return;
    int d = __ldg(dst + e);
    int pos = pre[d >> 10] + atomicAdd(&g_off[d], 1);
    g_edge[pos] = make_int2(__ldg(src + e), __ldg(ety + e));
}

// ---------------------------------------------------------------------------
// K4: one warp per node: z = (1/cnt) * sum_e (h[src_e] + rel[etype_e]);
// (R11/R13-proven chunk-4 float4 version); writes z as bf16 hi/lo.
// ---------------------------------------------------------------------------
__global__ void k_agg(const float* __restrict__ rel, int n, int nchunks)
{
    __shared__ int pre[128];
    load_prefix(pre, nchunks);

    int lane = threadIdx.x & 31;
    int node = (blockIdx.x * blockDim.x + threadIdx.x) >> 5;
    if (node >= n) return;
    int cnt = __ldg(&g_cnt[node]);
    int beg = pre[node >> 10] + __ldg(&g_off[node]) - cnt;

    const float4* h4 = reinterpret_cast<const float4*>(g_h);
    const float4* r4 = reinterpret_cast<const float4*>(rel);

    float4 acc = make_float4(0.f, 0.f, 0.f, 0.f);
    int j = 0;
    for (; j + 3 < cnt; j += 4) {
        int2 e0 = __ldg(&g_edge[beg + j]);
        int2 e1 = __ldg(&g_edge[beg + j + 1]);
        int2 e2 = __ldg(&g_edge[beg + j + 2]);
        int2 e3 = __ldg(&g_edge[beg + j + 3]);
        float4 a0 = __ldcg(h4 + e0.x * D4 + lane);
        float4 a1 = __ldcg(h4 + e1.x * D4 + lane);
        float4 a2 = __ldcg(h4 + e2.x * D4 + lane);
        float4 a3 = __ldcg(h4 + e3.x * D4 + lane);
        float4 b0 = __ldg(r4 + e0.y * D4 + lane);
        float4 b1 = __ldg(r4 + e1.y * D4 + lane);
        float4 b2 = __ldg(r4 + e2.y * D4 + lane);
        float4 b3 = __ldg(r4 + e3.y * D4 + lane);
        acc.x += ((a0.x + b0.x) + (a1.x + b1.x)) + ((a2.x + b2.x) + (a3.x + b3.x));
        acc.y += ((a0.y + b0.y) + (a1.y + b1.y)) + ((a2.y + b2.y) + (a3.y + b3.y));
        acc.z += ((a0.z + b0.z) + (a1.z + b1.z)) + ((a2.z + b2.z) + (a3.z + b3.z));
        acc.w += ((a0.w + b0.w) + (a1.w + b1.w)) + ((a2.w + b2.w) + (a3.w + b3.w));
    }
    for (; j < cnt; j++) {
        int2 e0 = __ldg(&g_edge[beg + j]);
        float4 a0 = __ldcg(h4 + e0.x * D4 + lane);
        float4 b0 = __ldg(r4 + e0.y * D4 + lane);
        acc.x += a0.x + b0.x;
        acc.y += a0.y + b0.y;
        acc.z += a0.z + b0.z;
        acc.w += a0.w + b0.w;
    }
    float inv = (cnt > 0) ? 1.0f / (float)cnt : 0.f;
    acc.x *= inv; acc.y *= inv; acc.z *= inv; acc.w *= inv;

    uint32_t h01, l01, h23, l23;
    split2(acc.x, acc.y, h01, l01);
    split2(acc.z, acc.w, h23, l23);
    int off = ((lane >> 1) ^ (node & 7)) * 16 + (lane & 1) * 8;
    *reinterpret_cast<uint2*>((char*)g_za + (size_t)node * 256 + off) = make_uint2(h01, h23);
    *reinterpret_cast<uint2*>((char*)g_zl + (size_t)node * 256 + off) = make_uint2(l01, l23);
}

// ===========================================================================
// K5: out = relu( z @ Wn + h @ Wl ) via mma.sync bf16-split (hh + hl + lh),
// SOFTWARE-PIPELINED (R13-proven): A in 4 x 32KB stages (z-hi, h-hi, z-lo,
// h-lo) ping-ponged through 2 slots; cp.async overlaps MMA; last stage
// prefetches next tile's z-hi. deg==0 -> relu(h @ We).
// ===========================================================================

#define OFF_BHI 0
#define OFF_BLO 65536
#define OFF_S0  131072
#define OFF_S1  163840
#define OFF_DEG 196608
#define SMEM_K5 (196608 + 512)

__device__ __forceinline__ uint32_t smem_u32(const void* p) {
    uint32_t a;
    asm("{ .reg .u64 t; cvta.to.shared.u64 t, %1; cvt.u32.u64 %0, t; }"
        : "=r"(a) : "l"(p));
    return a;
}
__device__ __forceinline__ void cpa16(uint32_t dst, const void* src) {
    asm volatile("cp.async.cg.shared.global [%0], [%1], 16;"
                 :: "r"(dst), "l"(src) : "memory");
}
__device__ __forceinline__ void ldsm4(uint32_t* r, uint32_t addr) {
    asm volatile("ldmatrix.sync.aligned.m8n8.x4.shared.b16 {%0,%1,%2,%3}, [%4];"
                 : "=r"(r[0]), "=r"(r[1]), "=r"(r[2]), "=r"(r[3]) : "r"(addr));
}
__device__ __forceinline__ void mma16816(float* c, const uint32_t* a,
                                         const uint32_t* b) {
    asm volatile("mma.sync.aligned.m16n8k16.row.col.f32.bf16.bf16.f32 "
                 "{%0,%1,%2,%3}, {%4,%5,%6,%7}, {%8,%9}, {%0,%1,%2,%3};"
                 : "+f"(c[0]), "+f"(c[1]), "+f"(c[2]), "+f"(c[3])
                 : "r"(a[0]), "r"(a[1]), "r"(a[2]), "r"(a[3]),
                   "r"(b[0]), "r"(b[1]));
}

__global__ void __launch_bounds__(512, 1)
k_out(const float* __restrict__ Wl, const float* __restrict__ We,
      const float* __restrict__ Wn, float* __restrict__ out, int n)
{
    extern __shared__ __align__(16) char smem[];
    int* degs = reinterpret_cast<int*>(smem + OFF_DEG);
    uint32_t sBhi = smem_u32(smem + OFF_BHI);
    uint32_t sBlo = smem_u32(smem + OFF_BLO);
    uint32_t slot[2] = { smem_u32(smem + OFF_S0), smem_u32(smem + OFF_S1) };

    int tid = threadIdx.x, lane = tid & 31, wid = tid >> 5;
    int wm = wid & 3, wn = wid >> 2;      // 4x4 warp grid: 32 rows x 32 cols
    int rr = lane & 7, q = lane >> 3;

    int ca_q = (q >> 1);
    int m0 = wm * 32 + (q & 1) * 8 + rr;
    int m1 = m0 + 16;

    // ---- stage B = [Wn; Wl] transposed to [n][k], hi/lo, swizzled (once) ----
    for (int i = tid; i < 128 * 32; i += 512) {
        int nn = i >> 5, c = i & 31;
        float v[8];
        #pragma unroll
        for (int j = 0; j < 8; j++) {
            int k = c * 8 + j;
            v[j] = (k < 128) ? __ldg(Wn + k * 128 + nn)
                             : __ldg(Wl + (k - 128) * 128 + nn);
        }
        uint32_t hi[4], lo[4];
        split2(v[0], v[1], hi[0], lo[0]);
        split2(v[2], v[3], hi[1], lo[1]);
        split2(v[4], v[5], hi[2], lo[2]);
        split2(v[6], v[7], hi[3], lo[3]);
        int cs = c ^ (nn & 7);
        *reinterpret_cast<uint4*>(smem + OFF_BHI + nn * 512 + cs * 16) =
            make_uint4(hi[0], hi[1], hi[2], hi[3]);
        *reinterpret_cast<uint4*>(smem + OFF_BLO + nn * 512 + cs * 16) =
            make_uint4(lo[0], lo[1], lo[2], lo[3]);
    }

    int ntile = (n + 127) / 128;

    // prologue: prefetch first tile's z-hi into slot0
    if ((int)blockIdx.x < ntile) {
        const char* s = (const char*)g_za + (size_t)blockIdx.x * 128 * 256;
        #pragma unroll
        for (int j = 0; j < 4; j++) {
            int idx = tid + j * 512;
            cpa16(slot[0] + idx * 16, s + idx * 16);
        }
    }
    asm volatile("cp.async.commit_group;" ::: "memory");

    for (int tile = blockIdx.x; tile < ntile; tile += gridDim.x) {
        size_t rb = (size_t)tile * 128 * 256;
        int row0 = tile * 128;

        // issue stage1 = h-hi -> slot1
        {
            const char* s = (const char*)g_ha + rb;
            #pragma unroll
            for (int j = 0; j < 4; j++) {
                int idx = tid + j * 512;
                cpa16(slot[1] + idx * 16, s + idx * 16);
            }
            asm volatile("cp.async.commit_group;" ::: "memory");
        }
        asm volatile("cp.async.wait_group 1;" ::: "memory");   // z-hi ready
        __syncthreads();

        if (tid < 128) {
            int gr = row0 + tid;
            int c = 1;
            if (gr < n) { c = g_cnt[gr]; g_cnt[gr] = 0; }
            degs[tid] = c;
        }

        float acc[2][4][4];
        #pragma unroll
        for (int mt = 0; mt < 2; mt++)
            #pragma unroll
            for (int nt = 0; nt < 4; nt++)
                #pragma unroll
                for (int j2 = 0; j2 < 4; j2++) acc[mt][nt][j2] = 0.f;

        // 4 stages: (slot0: z-hi, cb=0), (slot1: h-hi, cb=16),
        //           (slot0: z-lo, cb=0), (slot1: h-lo, cb=16)
        #pragma unroll
        for (int st = 0; st < 4; st++) {
            uint32_t Ab = slot[st & 1];
            int cb = (st & 1) ? 16 : 0;
            bool hiStage = (st < 2);

            #pragma unroll 1
            for (int kc = 0; kc < 8; kc++) {
                uint32_t a0[4], a1[4];
                int ca = kc * 2 + ca_q;
                ldsm4(a0, Ab + (uint32_t)(m0 * 256 + ((ca ^ (m0 & 7)) * 16)));
                ldsm4(a1, Ab + (uint32_t)(m1 * 256 + ((ca ^ (m1 & 7)) * 16)));
                #pragma unroll
                for (int nb = 0; nb < 2; nb++) {
                    int nn = wn * 32 + nb * 16 + (q >> 1) * 8 + rr;
                    int c = cb + kc * 2 + (q & 1);
                    uint32_t ob = (uint32_t)(nn * 512 + ((c ^ (nn & 7)) * 16));
                    uint32_t bh[4];
                    ldsm4(bh, sBhi + ob);
                    mma16816(acc[0][2 * nb],     a0, bh);
                    mma16816(acc[0][2 * nb + 1], a0, bh + 2);
                    mma16816(acc[1][2 * nb],     a1, bh);
                    mma16816(acc[1][2 * nb + 1], a1, bh + 2);
                    if (hiStage) {
                        uint32_t bl[4];
                        ldsm4(bl, sBlo + ob);
                        mma16816(acc[0][2 * nb],     a0, bl);
                        mma16816(acc[0][2 * nb + 1], a0, bl + 2);
                        mma16816(acc[1][2 * nb],     a1, bl);
                        mma16816(acc[1][2 * nb + 1], a1, bl + 2);
                    }
                }
            }

            if (st < 3) {
                __syncthreads();
                const char* s;
                if (st == 0)      s = (const char*)g_zl + rb;
                else if (st == 1) s = (const char*)g_la + rb;
                else {
                    int nt2 = tile + gridDim.x;
                    s = (nt2 < ntile)
                        ? (const char*)g_za + (size_t)nt2 * 128 * 256 : nullptr;
                }
                if (s) {
                    uint32_t dstSlot = slot[st & 1];
                    #pragma unroll
                    for (int j = 0; j < 4; j++) {
                        int idx = tid + j * 512;
                        cpa16(dstSlot + idx * 16, s + idx * 16);
                    }
                }
                asm volatile("cp.async.commit_group;" ::: "memory");
                asm volatile("cp.async.wait_group 1;" ::: "memory");
                __syncthreads();
            }
        }

        // ---- epilogue ----
        #pragma unroll
        for (int mt = 0; mt < 2; mt++) {
            #pragma unroll
            for (int half = 0; half < 2; half++) {
                int rl = wm * 32 + mt * 16 + half * 8 + (lane >> 2);
                int gr = row0 + rl;
                if (gr >= n) continue;
                if (degs[rl] != 0) {
                    #pragma unroll
                    for (int nt = 0; nt < 4; nt++) {
                        float a0 = acc[mt][nt][2 * half];
                        float a1 = acc[mt][nt][2 * half + 1];
                        float2 o = make_float2(a0 > 0.f ? a0 : 0.f,
                                               a1 > 0.f ? a1 : 0.f);
                        *reinterpret_cast<float2*>(
                            out + (size_t)gr * 128 + wn * 32 + nt * 8 + (lane & 3) * 2) = o;
                    }
                } else {
                    int cbase = (lane & 3) * 2;
                    #pragma unroll 1
                    for (int nt = 0; nt < 4; nt++) {
                        float f0 = 0.f, f1 = 0.f;
                        int col = wn * 32 + nt * 8 + cbase;
                        #pragma unroll 1
                        for (int k = 0; k < 128; k++) {
                            float hk = g_h[(size_t)gr * 128 + k];
                            f0 += hk * __ldg(We + k * 128 + col);
                            f1 += hk * __ldg(We + k * 128 + col + 1);
                        }
                        float2 o = make_float2(f0 > 0.f ? f0 : 0.f,
                                               f1 > 0.f ? f1 : 0.f);
                        *reinterpret_cast<float2*>(
                            out + (size_t)gr * 128 + col) = o;
                    }
                }
            }
        }
        __syncthreads();
    }
}

// ---------------------------------------------------------------------------
extern "C" void kernel_launch(void* const* d_in, const int* in_sizes, int n_in,
                              void* d_out, int out_size)
{
    const float* prev    = (const float*)d_in[0];
    const float* rel     = (const float*)d_in[1];
    const float* Wl      = (const float*)d_in[2];
    const float* We      = (const float*)d_in[3];
    const float* Wn      = (const float*)d_in[4];
    const int*   node_id = (const int*)d_in[5];
    const int*   src     = (const int*)d_in[6];
    const int*   dst     = (const int*)d_in[7];
    const int*   ety     = (const int*)d_in[8];
    float* out = (float*)d_out;

    int n_nodes = in_sizes[5];
    int n_edges = in_sizes[6];
    int nchunks = (n_nodes + 1023) / 1024;

    int gb = (n_nodes * D4 + 255) / 256;
    int hb = (n_edges + 255) / 256;
    k_prep<<<gb + hb, 256>>>(prev, node_id, dst, n_nodes, n_edges, gb);

    k_scan1<<<nchunks, 1024>>>(n_nodes);

    k_perm<<<(n_edges + 255) / 256, 256>>>(src, dst, ety, n_edges, nchunks);

    k_agg<<<(n_nodes * 32 + 255) / 256, 256>>>(rel, n_nodes, nchunks);

    cudaFuncSetAttribute(k_out, cudaFuncAttributeMaxDynamicSharedMemorySize,
                         SMEM_K5);
    k_out<<<148, 512, SMEM_K5>>>(Wl, We, Wn, out, n_nodes);
}